// round 6
// baseline (speedup 1.0000x reference)
#include <cuda_runtime.h>

#define NN       50000
#define HC       128
#define NEG      0.2f
#define SCAP     256
#define MAXTGT   1024
#define LCAP     32768
#define BMWORDS  ((NN + 31) / 32)

// ---------------- device scratch ----------------
__device__ unsigned g_bitmap[BMWORDS];
__device__ int      g_nodelist[SCAP];
__device__ int      g_tgt_src[MAXTGT];
__device__ float    g_tgt_a[MAXTGT];
__device__ int      g_Lslot[LCAP];
__device__ float    g_Lxs[LCAP];
__device__ float2   g_Llg[LCAP];
__device__ unsigned g_maxkey[2 * SCAP];
__device__ float    g_h1[SCAP * HC];
__device__ float    g_xl2[SCAP * HC];
__device__ float    g_xr2t[HC];
__device__ int      g_tcount, g_nnodes, g_lcount;
__device__ double   g_easum;
__device__ float    g_fill;
__device__ float    g_sink;

__device__ __forceinline__ unsigned fenc(float f) {
    unsigned u = __float_as_uint(f);
    return (u & 0x80000000u) ? ~u : (u | 0x80000000u);
}
__device__ __forceinline__ float fdec(unsigned k) {
    return __uint_as_float((k & 0x80000000u) ? (k ^ 0x80000000u) : ~k);
}
__device__ __forceinline__ float lrelu(float v) { return v > 0.f ? v : NEG * v; }

// ---------------- K0: reset + L2 weight prefetch ----------------
__global__ void k_reset(const int* tgtp,
                        const float* __restrict__ Wl2, const float* __restrict__ Wr2,
                        const float* __restrict__ Wfc,
                        const float* __restrict__ Wl1, const float* __restrict__ Wr1,
                        const float* __restrict__ We1, const float* __restrict__ att1,
                        const float* __restrict__ bl1, const float* __restrict__ br1) {
    int tid = threadIdx.x;
    if (blockIdx.x < 8) {
        int tgt = *tgtp;
        int i = blockIdx.x * blockDim.x + tid;
        int stride = 8 * blockDim.x;
        int tw = tgt >> 5;
        for (int j = i; j < BMWORDS; j += stride)
            g_bitmap[j] = (j == tw) ? (1u << (tgt & 31)) : 0u;
        for (int j = i; j < 2 * SCAP; j += stride) g_maxkey[j] = 0u;
        if (i == 0) {
            g_tcount = 0; g_nnodes = 1; g_lcount = 0; g_easum = 0.0;
            g_nodelist[0] = tgt;
        }
    } else if (blockIdx.x < 56) {
        // pull Wl2/Wr2/Wfc into L2 while scans run
        int b = blockIdx.x - 8;               // 0..47
        const float* W = (b % 3 == 0) ? Wl2 : (b % 3 == 1) ? Wr2 : Wfc;
        int nb = 16, sub = b / 3;
        const float4* W4 = (const float4*)W;
        float acc = 0.f;
        int nv = (HC * HC) / 4;
        for (int j = sub * blockDim.x + tid; j < nv; j += nb * blockDim.x) {
            float4 v = W4[j];
            acc += v.x + v.y + v.z + v.w;
        }
        if (acc == 123456789.0f) g_sink = acc;
    } else {
        // conv1 weight group (6 x 512B) -> L2 for scan2's inline logits
        float acc = 0.f;
        if (tid < HC) {
            acc = Wl1[tid] + Wr1[tid] + We1[tid] + att1[tid] + bl1[tid] + br1[tid];
        }
        if (acc == 123456789.0f) g_sink = acc;
    }
}

// ---------------- K1: scan edges: ea mean + target in-edges + flag sources ----------------
__global__ void k_scan1(const int* __restrict__ src, const int* __restrict__ dst,
                        const float* __restrict__ ea, const int* tgtp, int E) {
    int tgt = *tgtp;
    int i = blockIdx.x * blockDim.x + threadIdx.x;
    int stride = gridDim.x * blockDim.x;
    int nv = E >> 2;
    const int4* d4 = (const int4*)dst;
    const float4* a4 = (const float4*)ea;
    double acc = 0.0;
    for (int v = i; v < nv; v += stride) {
        int4 d = d4[v];
        float4 a = a4[v];
        acc += (double)a.x + (double)a.y + (double)a.z + (double)a.w;
        int e = v << 2;
        #pragma unroll
        for (int c = 0; c < 4; c++) {
            int dd = (c == 0) ? d.x : (c == 1) ? d.y : (c == 2) ? d.z : d.w;
            if (dd == tgt) {
                float aa = (c == 0) ? a.x : (c == 1) ? a.y : (c == 2) ? a.z : a.w;
                int idx = atomicAdd(&g_tcount, 1);
                int s = src[e + c];
                if (idx < MAXTGT) { g_tgt_src[idx] = s; g_tgt_a[idx] = aa; }
                unsigned m = 1u << (s & 31);
                unsigned old = atomicOr(&g_bitmap[s >> 5], m);
                if (!(old & m)) {
                    int sl = atomicAdd(&g_nnodes, 1);
                    if (sl < SCAP) g_nodelist[sl] = s;
                }
            }
        }
    }
    for (int e = (nv << 2) + i; e < E; e += stride) {
        acc += (double)ea[e];
        if (dst[e] == tgt) {
            int idx = atomicAdd(&g_tcount, 1);
            int s = src[e];
            if (idx < MAXTGT) { g_tgt_src[idx] = s; g_tgt_a[idx] = ea[e]; }
            unsigned m = 1u << (s & 31);
            unsigned old = atomicOr(&g_bitmap[s >> 5], m);
            if (!(old & m)) {
                int sl = atomicAdd(&g_nnodes, 1);
                if (sl < SCAP) g_nodelist[sl] = s;
            }
        }
    }
    __shared__ double sd[256];
    sd[threadIdx.x] = acc; __syncthreads();
    for (int off = blockDim.x >> 1; off; off >>= 1) {
        if (threadIdx.x < off) sd[threadIdx.x] += sd[threadIdx.x + off];
        __syncthreads();
    }
    if (threadIdx.x == 0) atomicAdd(&g_easum, sd[0]);
}

// ---------------- inline conv1 logit on a hit edge ----------------
__device__ __forceinline__ void hit_edge(
        int dd, int sn, float a, const float* __restrict__ x,
        const float* __restrict__ Wl1, const float* __restrict__ bl1,
        const float* __restrict__ Wr1, const float* __restrict__ br1,
        const float* __restrict__ We1, const float* __restrict__ att1,
        const int* snl, int nn) {
    int slot = 0;
    for (int t = 0; t < nn; t++) { if (snl[t] == dd) { slot = t; break; } }
    float xs = __ldg(x + sn);
    float xd = __ldg(x + dd);
    float p0 = 0.f, p1 = 0.f;
    #pragma unroll 16
    for (int j = 0; j < HC; j++) {
        float bb = __ldg(bl1 + j) + __ldg(br1 + j);
        float v = fmaf(xs, __ldg(Wl1 + j),
                  fmaf(a, __ldg(We1 + j),
                  fmaf(xd, __ldg(Wr1 + j), bb)));
        v = lrelu(v);
        float p = v * __ldg(att1 + j);
        if (j < 64) p0 += p; else p1 += p;
    }
    int idx = atomicAdd(&g_lcount, 1);
    if (idx < LCAP) {
        g_Lslot[idx] = slot; g_Lxs[idx] = xs; g_Llg[idx] = make_float2(p0, p1);
    }
    atomicMax(&g_maxkey[2 * slot],     fenc(p0));
    atomicMax(&g_maxkey[2 * slot + 1], fenc(p1));
}

// ---------------- K2: collect + inline conv1 logits ----------------
__global__ void k_scan2(const int* __restrict__ src, const int* __restrict__ dst,
                        const float* __restrict__ ea, const float* __restrict__ x,
                        const float* __restrict__ Wl1, const float* __restrict__ bl1,
                        const float* __restrict__ Wr1, const float* __restrict__ br1,
                        const float* __restrict__ We1, const float* __restrict__ att1,
                        int E) {
    __shared__ unsigned sbm[BMWORDS];
    __shared__ int snl[SCAP];
    __shared__ int snn;
    int tid = threadIdx.x;
    int i = blockIdx.x * blockDim.x + tid;
    if (i == 0) g_fill = (float)(g_easum / (double)E);
    int stride = gridDim.x * blockDim.x;

    for (int j = tid; j < BMWORDS; j += blockDim.x) sbm[j] = g_bitmap[j];
    if (tid == 0) snn = min(g_nnodes, SCAP);
    __syncthreads();
    int nn = snn;
    for (int j = tid; j < nn; j += blockDim.x) snl[j] = g_nodelist[j];
    __syncthreads();

    int nv = E >> 2;
    const int4* d4 = (const int4*)dst;
    for (int v = i; v < nv; v += stride) {
        int4 d = d4[v];
        int e = v << 2;
        #pragma unroll
        for (int c = 0; c < 4; c++) {
            int dd = (c == 0) ? d.x : (c == 1) ? d.y : (c == 2) ? d.z : d.w;
            if ((sbm[dd >> 5] >> (dd & 31)) & 1u)
                hit_edge(dd, src[e + c], ea[e + c], x,
                         Wl1, bl1, Wr1, br1, We1, att1, snl, nn);
        }
    }
    for (int e = (nv << 2) + i; e < E; e += stride) {
        int dd = dst[e];
        if ((sbm[dd >> 5] >> (dd & 31)) & 1u)
            hit_edge(dd, src[e], ea[e], x,
                     Wl1, bl1, Wr1, br1, We1, att1, snl, nn);
    }
}

// ---------------- K3: conv1 stats — self-loops + exp sums + h1 ----------------
__global__ void __launch_bounds__(512) k_stats(
        const float* __restrict__ x,
        const float* __restrict__ Wl1, const float* __restrict__ bl1,
        const float* __restrict__ Wr1, const float* __restrict__ br1,
        const float* __restrict__ We1, const float* __restrict__ att1,
        const float* __restrict__ b1) {
    int tid = threadIdx.x;
    int nn = min(g_nnodes, SCAP);
    int lc = min(g_lcount, LCAP);
    float fill = g_fill;

    __shared__ float sWl1[HC], sWr1[HC], sWe1[HC], sAtt1[HC], sBlr[HC];
    __shared__ float sxd[SCAP];
    __shared__ float2 sslg[SCAP];
    __shared__ unsigned smax[2 * SCAP];
    __shared__ float ssum[4 * SCAP];

    if (tid < HC) {
        sWl1[tid] = Wl1[tid]; sWr1[tid] = Wr1[tid]; sWe1[tid] = We1[tid];
        sAtt1[tid] = att1[tid];
        sBlr[tid] = bl1[tid] + br1[tid];
    }
    for (int j = tid; j < nn; j += 512) {
        sxd[j] = x[g_nodelist[j]];
        smax[2 * j]     = g_maxkey[2 * j];
        smax[2 * j + 1] = g_maxkey[2 * j + 1];
        ssum[4 * j] = 0.f; ssum[4 * j + 1] = 0.f;
        ssum[4 * j + 2] = 0.f; ssum[4 * j + 3] = 0.f;
    }
    __syncthreads();

    // self-loop logits: thread-per-slot
    for (int s = tid; s < nn; s += 512) {
        float xs = sxd[s];
        float p0 = 0.f, p1 = 0.f;
        #pragma unroll 16
        for (int j = 0; j < HC; j++) {
            float v = fmaf(xs, sWl1[j] + sWr1[j], fmaf(fill, sWe1[j], sBlr[j]));
            v = lrelu(v);
            float p = v * sAtt1[j];
            if (j < 64) p0 += p; else p1 += p;
        }
        sslg[s] = make_float2(p0, p1);
        atomicMax(&smax[2 * s],     fenc(p0));
        atomicMax(&smax[2 * s + 1], fenc(p1));
    }
    __syncthreads();

    // exp sums: edges then self items
    for (int i = tid; i < lc + nn; i += 512) {
        int slot; float xs; float2 l;
        if (i < lc) { slot = g_Lslot[i]; xs = g_Lxs[i]; l = g_Llg[i]; }
        else        { slot = i - lc; xs = sxd[slot]; l = sslg[slot]; }
        float e0 = expf(l.x - fdec(smax[2 * slot]));
        float e1 = expf(l.y - fdec(smax[2 * slot + 1]));
        atomicAdd(&ssum[4 * slot],     e0);
        atomicAdd(&ssum[4 * slot + 1], e1);
        atomicAdd(&ssum[4 * slot + 2], e0 * xs);
        atomicAdd(&ssum[4 * slot + 3], e1 * xs);
    }
    __syncthreads();

    // h1[slot][c] = relu(Wl1[c] * S_head(c) + bl1[c] + b1[c])
    for (int idx = tid; idx < nn * HC; idx += 512) {
        int s = idx >> 7, c = idx & 127;
        float S = (c < 64) ? ssum[4 * s + 2] / ssum[4 * s]
                           : ssum[4 * s + 3] / ssum[4 * s + 1];
        g_h1[idx] = fmaxf(fmaf(sWl1[c], S, bl1[c] + b1[c]), 0.f);
    }
}

// ---------------- K4: parallel GEMM — xl2 (block per slot) + xr2t (block 63) ----------------
__global__ void __launch_bounds__(512) k_gemm(
        const float* __restrict__ Wl2, const float* __restrict__ bl2,
        const float* __restrict__ Wr2, const float* __restrict__ br2) {
    int tid = threadIdx.x, c = tid & 127, q = tid >> 7;
    int nn = min(g_nnodes, SCAP);
    __shared__ float sh[HC];
    __shared__ float sred[3][HC];

    if (blockIdx.x < 63) {
        for (int s = blockIdx.x; s < nn; s += 63) {
            if (tid < HC) sh[tid] = g_h1[s * HC + tid];
            __syncthreads();
            float acc = 0.f;
            const float* W = Wl2 + (q * 32) * HC + c;
            #pragma unroll
            for (int k = 0; k < 32; k++)
                acc = fmaf(sh[q * 32 + k], W[k * HC], acc);
            if (q > 0) sred[q - 1][c] = acc;
            __syncthreads();
            if (q == 0)
                g_xl2[s * HC + c] = acc + sred[0][c] + sred[1][c] + sred[2][c] + bl2[c];
            __syncthreads();
        }
    } else {
        if (tid < HC) sh[tid] = g_h1[tid];     // slot 0 == target
        __syncthreads();
        float acc = 0.f;
        const float* W = Wr2 + (q * 32) * HC + c;
        #pragma unroll
        for (int k = 0; k < 32; k++)
            acc = fmaf(sh[q * 32 + k], W[k * HC], acc);
        if (q > 0) sred[q - 1][c] = acc;
        __syncthreads();
        if (q == 0)
            g_xr2t[c] = acc + sred[0][c] + sred[1][c] + sred[2][c] + br2[c];
    }
}

// ---------------- K5: conv2 at target + fc ----------------
__global__ void __launch_bounds__(512) k_final(
        const float* __restrict__ We2, const float* __restrict__ att2,
        const float* __restrict__ b2,
        const float* __restrict__ Wfc, const float* __restrict__ bfc,
        float* __restrict__ out) {
    int tid = threadIdx.x, lane = tid & 31, w = tid >> 5;
    int c = tid & 127, q = tid >> 7;
    int nn = min(g_nnodes, SCAP);
    int tc = min(g_tcount, MAXTGT);
    int items = tc + 1;

    __shared__ float sxr[HC], sO[HC];
    __shared__ float sred[3][HC];
    __shared__ int   snl[SCAP];
    __shared__ float2 slg[MAXTGT + 1];
    __shared__ float sal0[MAXTGT + 1], sal1[MAXTGT + 1];
    __shared__ int   sslot[MAXTGT + 1];
    __shared__ unsigned tmax0, tmax1;
    __shared__ float tsum0, tsum1;

    if (tid < HC) sxr[tid] = g_xr2t[tid];
    for (int j = tid; j < nn; j += 512) snl[j] = g_nodelist[j];
    if (tid == 0) { tmax0 = 0u; tmax1 = 0u; tsum0 = 0.f; tsum1 = 0.f; }
    __syncthreads();

    for (int i = w; i < items; i += 16) {
        int slot = 0; float a;
        if (i < tc) {
            int sn = g_tgt_src[i];
            for (int t = 0; t < nn; t++) { if (snl[t] == sn) { slot = t; break; } }
            a = g_tgt_a[i];
        } else { slot = 0; a = g_fill; }
        float p0 = 0.f, p1 = 0.f;
        #pragma unroll
        for (int k = 0; k < 4; k++) {
            int cc = lane + 32 * k;
            float v = g_xl2[slot * HC + cc] + sxr[cc] + a * We2[cc];
            v = lrelu(v);
            float p = v * att2[cc];
            if (k < 2) p0 += p; else p1 += p;
        }
        #pragma unroll
        for (int off = 16; off; off >>= 1) {
            p0 += __shfl_down_sync(0xffffffffu, p0, off);
            p1 += __shfl_down_sync(0xffffffffu, p1, off);
        }
        if (lane == 0) {
            slg[i] = make_float2(p0, p1);
            sslot[i] = slot;
            atomicMax(&tmax0, fenc(p0));
            atomicMax(&tmax1, fenc(p1));
        }
    }
    __syncthreads();
    float m0 = fdec(tmax0), m1 = fdec(tmax1);
    for (int i = tid; i < items; i += 512) {
        float2 l = slg[i];
        float e0 = expf(l.x - m0), e1 = expf(l.y - m1);
        sal0[i] = e0; sal1[i] = e1;
        atomicAdd(&tsum0, e0); atomicAdd(&tsum1, e1);
    }
    __syncthreads();

    float inv = (c < 64) ? (1.f / tsum0) : (1.f / tsum1);
    float agg = 0.f;
    for (int i = q; i < items; i += 4) {
        float al = ((c < 64) ? sal0[i] : sal1[i]) * inv;
        agg = fmaf(al, g_xl2[sslot[i] * HC + c], agg);
    }
    if (q > 0) sred[q - 1][c] = agg;
    __syncthreads();
    if (q == 0) sO[c] = agg + sred[0][c] + sred[1][c] + sred[2][c] + b2[c];
    __syncthreads();

    float r = 0.f;
    const float* Wf = Wfc + (q * 32) * HC + c;
    #pragma unroll
    for (int k = 0; k < 32; k++)
        r = fmaf(sO[q * 32 + k], Wf[k * HC], r);
    if (q > 0) sred[q - 1][c] = r;
    __syncthreads();
    if (q == 0) out[c] = r + sred[0][c] + sred[1][c] + sred[2][c] + bfc[c];
}

// ---------------- launch ----------------
extern "C" void kernel_launch(void* const* d_in, const int* in_sizes, int n_in,
                              void* d_out, int out_size) {
    const float* x    = (const float*)d_in[0];
    const int*   ei   = (const int*)  d_in[1];
    const float* ea   = (const float*)d_in[2];
    const int*   tgtp = (const int*)  d_in[3];
    const float* Wl1  = (const float*)d_in[4];
    const float* bl1  = (const float*)d_in[5];
    const float* Wr1  = (const float*)d_in[6];
    const float* br1  = (const float*)d_in[7];
    const float* We1  = (const float*)d_in[8];
    const float* att1 = (const float*)d_in[9];
    const float* b1   = (const float*)d_in[10];
    const float* Wl2  = (const float*)d_in[11];
    const float* bl2  = (const float*)d_in[12];
    const float* Wr2  = (const float*)d_in[13];
    const float* br2  = (const float*)d_in[14];
    const float* We2  = (const float*)d_in[15];
    const float* att2 = (const float*)d_in[16];
    const float* b2   = (const float*)d_in[17];
    const float* Wfc  = (const float*)d_in[18];
    const float* bfc  = (const float*)d_in[19];
    float* out = (float*)d_out;

    int E = in_sizes[1] / 2;
    const int* src = ei;
    const int* dst = ei + E;

    k_reset<<<64, 256>>>(tgtp, Wl2, Wr2, Wfc, Wl1, Wr1, We1, att1, bl1, br1);
    k_scan1<<<592, 256>>>(src, dst, ea, tgtp, E);
    k_scan2<<<592, 256>>>(src, dst, ea, x, Wl1, bl1, Wr1, br1, We1, att1, E);
    k_stats<<<1, 512>>>(x, Wl1, bl1, Wr1, br1, We1, att1, b1);
    k_gemm <<<64, 512>>>(Wl2, bl2, Wr2, br2);
    k_final<<<1, 512>>>(We2, att2, b2, Wfc, bfc, out);
    (void)n_in; (void)out_size;
}

// round 7
// speedup vs baseline: 1.2321x; 1.2321x over previous
#include <cuda_runtime.h>

#define NN       50000
#define HC       128
#define NEG      0.2f
#define SCAP     256
#define MAXTGT   1024
#define LCAP     32768
#define BMWORDS  ((NN + 31) / 32)
#define TB       64               // tail blocks
#define TT       512              // tail threads/block

// ---------------- device scratch ----------------
__device__ unsigned g_bitmap[BMWORDS];
__device__ int      g_nodelist[SCAP];
__device__ int      g_tgt_src[MAXTGT];
__device__ float    g_tgt_a[MAXTGT];
__device__ int      g_Lslot[LCAP];
__device__ float    g_Lxs[LCAP];
__device__ float    g_La[LCAP];
__device__ unsigned g_maxkey[2 * SCAP];
__device__ float    g_ssum[4 * SCAP];
__device__ float    g_xl2[SCAP * HC];
__device__ float    g_xr2t[HC];
__device__ int      g_tcount, g_nnodes, g_lcount;
__device__ double   g_easum;
__device__ float    g_fill;
__device__ float    g_sink;
__device__ int      g_bar1, g_bar2, g_bar3;

__device__ __forceinline__ unsigned fenc(float f) {
    unsigned u = __float_as_uint(f);
    return (u & 0x80000000u) ? ~u : (u | 0x80000000u);
}
__device__ __forceinline__ float fdec(unsigned k) {
    return __uint_as_float((k & 0x80000000u) ? (k ^ 0x80000000u) : ~k);
}
__device__ __forceinline__ float lrelu(float v) { return v > 0.f ? v : NEG * v; }

__device__ __forceinline__ void grid_barrier(int* ctr) {
    __syncthreads();
    if (threadIdx.x == 0) {
        __threadfence();
        atomicAdd(ctr, 1);
        volatile int* v = ctr;
        while (*v < TB) { }
        __threadfence();
    }
    __syncthreads();
}

// ---------------- K0: reset + L2 weight prefetch ----------------
__global__ void k_reset(const int* tgtp,
                        const float* __restrict__ Wl2, const float* __restrict__ Wr2,
                        const float* __restrict__ Wfc) {
    int tid = threadIdx.x;
    if (blockIdx.x < 8) {
        int tgt = *tgtp;
        int i = blockIdx.x * blockDim.x + tid;
        int stride = 8 * blockDim.x;
        int tw = tgt >> 5;
        for (int j = i; j < BMWORDS; j += stride)
            g_bitmap[j] = (j == tw) ? (1u << (tgt & 31)) : 0u;
        for (int j = i; j < 2 * SCAP; j += stride) g_maxkey[j] = 0u;
        for (int j = i; j < 4 * SCAP; j += stride) g_ssum[j] = 0.f;
        if (i == 0) {
            g_tcount = 0; g_nnodes = 1; g_lcount = 0; g_easum = 0.0;
            g_nodelist[0] = tgt;
            g_bar1 = 0; g_bar2 = 0; g_bar3 = 0;
        }
    } else {
        // pull Wl2/Wr2/Wfc into L2 while scans run
        int b = blockIdx.x - 8;               // 0..55
        const float* W = (b % 3 == 0) ? Wl2 : (b % 3 == 1) ? Wr2 : Wfc;
        int nb = 56 / 3, sub = b / 3;
        const float4* W4 = (const float4*)W;
        float acc = 0.f;
        int nv = (HC * HC) / 4;
        for (int j = sub * blockDim.x + tid; j < nv; j += nb * blockDim.x) {
            float4 v = W4[j];
            acc += v.x + v.y + v.z + v.w;
        }
        if (acc == 123456789.0f) g_sink = acc;
    }
}

// ---------------- K1: scan edges: ea mean + target in-edges + flag sources ----------------
__global__ void k_scan1(const int* __restrict__ src, const int* __restrict__ dst,
                        const float* __restrict__ ea, const int* tgtp, int E) {
    int tgt = *tgtp;
    int i = blockIdx.x * blockDim.x + threadIdx.x;
    int stride = gridDim.x * blockDim.x;
    int nv = E >> 2;
    const int4* d4 = (const int4*)dst;
    const float4* a4 = (const float4*)ea;
    double ax = 0.0, ay = 0.0, az = 0.0, aw = 0.0;   // 4 independent chains
    for (int v = i; v < nv; v += stride) {
        int4 d = d4[v];
        float4 a = a4[v];
        ax += (double)a.x; ay += (double)a.y; az += (double)a.z; aw += (double)a.w;
        int e = v << 2;
        #pragma unroll
        for (int c = 0; c < 4; c++) {
            int dd = (c == 0) ? d.x : (c == 1) ? d.y : (c == 2) ? d.z : d.w;
            if (dd == tgt) {
                float aa = (c == 0) ? a.x : (c == 1) ? a.y : (c == 2) ? a.z : a.w;
                int idx = atomicAdd(&g_tcount, 1);
                int s = src[e + c];
                if (idx < MAXTGT) { g_tgt_src[idx] = s; g_tgt_a[idx] = aa; }
                unsigned m = 1u << (s & 31);
                unsigned old = atomicOr(&g_bitmap[s >> 5], m);
                if (!(old & m)) {
                    int sl = atomicAdd(&g_nnodes, 1);
                    if (sl < SCAP) g_nodelist[sl] = s;
                }
            }
        }
    }
    for (int e = (nv << 2) + i; e < E; e += stride) {
        ax += (double)ea[e];
        if (dst[e] == tgt) {
            int idx = atomicAdd(&g_tcount, 1);
            int s = src[e];
            if (idx < MAXTGT) { g_tgt_src[idx] = s; g_tgt_a[idx] = ea[e]; }
            unsigned m = 1u << (s & 31);
            unsigned old = atomicOr(&g_bitmap[s >> 5], m);
            if (!(old & m)) {
                int sl = atomicAdd(&g_nnodes, 1);
                if (sl < SCAP) g_nodelist[sl] = s;
            }
        }
    }
    __shared__ double sd[256];
    sd[threadIdx.x] = (ax + ay) + (az + aw); __syncthreads();
    for (int off = blockDim.x >> 1; off; off >>= 1) {
        if (threadIdx.x < off) sd[threadIdx.x] += sd[threadIdx.x + off];
        __syncthreads();
    }
    if (threadIdx.x == 0) atomicAdd(&g_easum, sd[0]);
}

// ---------------- K2: collect edges into flagged nodes (shared bitmap) ----------------
__global__ void k_scan2(const int* __restrict__ src, const int* __restrict__ dst,
                        const float* __restrict__ ea, const float* __restrict__ x, int E) {
    __shared__ unsigned sbm[BMWORDS];
    __shared__ int snl[SCAP];
    __shared__ int snn;
    int tid = threadIdx.x;
    int i = blockIdx.x * blockDim.x + tid;
    if (i == 0) g_fill = (float)(g_easum / (double)E);
    int stride = gridDim.x * blockDim.x;

    for (int j = tid; j < BMWORDS; j += blockDim.x) sbm[j] = g_bitmap[j];
    if (tid == 0) snn = min(g_nnodes, SCAP);
    __syncthreads();
    int nn = snn;
    for (int j = tid; j < nn; j += blockDim.x) snl[j] = g_nodelist[j];
    __syncthreads();

    int nv = E >> 2;
    const int4* d4 = (const int4*)dst;
    for (int v = i; v < nv; v += stride) {
        int4 d = d4[v];
        int e = v << 2;
        #pragma unroll
        for (int c = 0; c < 4; c++) {
            int dd = (c == 0) ? d.x : (c == 1) ? d.y : (c == 2) ? d.z : d.w;
            if ((sbm[dd >> 5] >> (dd & 31)) & 1u) {
                int slot = 0;
                for (int t = 0; t < nn; t++) { if (snl[t] == dd) { slot = t; break; } }
                int idx = atomicAdd(&g_lcount, 1);
                if (idx < LCAP) {
                    g_Lslot[idx] = slot;
                    g_Lxs[idx]   = x[src[e + c]];
                    g_La[idx]    = ea[e + c];
                }
            }
        }
    }
    for (int e = (nv << 2) + i; e < E; e += stride) {
        int dd = dst[e];
        if ((sbm[dd >> 5] >> (dd & 31)) & 1u) {
            int slot = 0;
            for (int t = 0; t < nn; t++) { if (snl[t] == dd) { slot = t; break; } }
            int idx = atomicAdd(&g_lcount, 1);
            if (idx < LCAP) {
                g_Lslot[idx] = slot; g_Lxs[idx] = x[src[e]]; g_La[idx] = ea[e];
            }
        }
    }
}

// ---------------- K3: fused tail — stats + gemm + conv2/fc, one kernel ----------------
__global__ void __launch_bounds__(TT) k_tail(
        const float* __restrict__ x,
        const float* __restrict__ Wl1, const float* __restrict__ bl1,
        const float* __restrict__ Wr1, const float* __restrict__ br1,
        const float* __restrict__ We1, const float* __restrict__ att1,
        const float* __restrict__ b1,
        const float* __restrict__ Wl2, const float* __restrict__ bl2,
        const float* __restrict__ Wr2, const float* __restrict__ br2,
        const float* __restrict__ We2, const float* __restrict__ att2,
        const float* __restrict__ b2,
        const float* __restrict__ Wfc, const float* __restrict__ bfc,
        float* __restrict__ out) {
    int tid = threadIdx.x, bid = blockIdx.x;
    int gtid = bid * TT + tid;
    int nn = min(g_nnodes, SCAP);
    int lc = min(g_lcount, LCAP);
    int total = lc + nn;
    float fill = g_fill;

    __shared__ float sWl1[HC], sWr1[HC], sWe1[HC], sAtt1[HC], sBlr[HC];
    if (tid < HC) {
        sWl1[tid] = Wl1[tid]; sWr1[tid] = Wr1[tid]; sWe1[tid] = We1[tid];
        sAtt1[tid] = att1[tid];
        sBlr[tid] = bl1[tid] + br1[tid];
    }
    __syncthreads();

    // ---- phase 1: thread-per-item logits + global per-slot max ----
    int   islot[2]; float ixs[2], ilg0[2], ilg1[2];
    int   nit = 0;
    for (int i = gtid; i < total; i += TB * TT) {
        int slot; float xs, a;
        if (i < lc) { slot = g_Lslot[i]; xs = g_Lxs[i]; a = g_La[i]; }
        else        { slot = i - lc;     xs = x[g_nodelist[slot]]; a = fill; }
        float xd = x[g_nodelist[slot]];
        float p0 = 0.f, p1 = 0.f;
        #pragma unroll 8
        for (int j = 0; j < HC; j++) {
            float v = fmaf(xs, sWl1[j], fmaf(a, sWe1[j], fmaf(xd, sWr1[j], sBlr[j])));
            v = lrelu(v);
            float p = v * sAtt1[j];
            if (j < 64) p0 += p; else p1 += p;
        }
        atomicMax(&g_maxkey[2 * slot],     fenc(p0));
        atomicMax(&g_maxkey[2 * slot + 1], fenc(p1));
        if (nit < 2) { islot[nit] = slot; ixs[nit] = xs; ilg0[nit] = p0; ilg1[nit] = p1; nit++; }
    }
    grid_barrier(&g_bar1);

    // ---- phase 2: exp sums (same threads, registers reused) ----
    for (int k = 0; k < nit; k++) {
        int slot = islot[k];
        float e0 = expf(ilg0[k] - fdec(g_maxkey[2 * slot]));
        float e1 = expf(ilg1[k] - fdec(g_maxkey[2 * slot + 1]));
        atomicAdd(&g_ssum[4 * slot],     e0);
        atomicAdd(&g_ssum[4 * slot + 1], e1);
        atomicAdd(&g_ssum[4 * slot + 2], e0 * ixs[k]);
        atomicAdd(&g_ssum[4 * slot + 3], e1 * ixs[k]);
    }
    grid_barrier(&g_bar2);

    // ---- phase 3: gemm per slot (blocks 0..62), xr2t (block 63) ----
    {
        int c = tid & 127, q = tid >> 7;
        __shared__ float sh[HC];
        __shared__ float sred[3][HC];
        if (bid < TB - 1) {
            for (int s = bid; s < nn; s += TB - 1) {
                if (tid < HC) {
                    float S = (tid < 64) ? g_ssum[4 * s + 2] / g_ssum[4 * s]
                                         : g_ssum[4 * s + 3] / g_ssum[4 * s + 1];
                    sh[tid] = fmaxf(fmaf(sWl1[tid], S, bl1[tid] + b1[tid]), 0.f);
                }
                __syncthreads();
                float acc = 0.f;
                const float* W = Wl2 + (q * 32) * HC + c;
                #pragma unroll
                for (int k = 0; k < 32; k++)
                    acc = fmaf(sh[q * 32 + k], W[k * HC], acc);
                if (q > 0) sred[q - 1][c] = acc;
                __syncthreads();
                if (q == 0)
                    g_xl2[s * HC + c] = acc + sred[0][c] + sred[1][c] + sred[2][c] + bl2[c];
                __syncthreads();
            }
        } else {
            if (tid < HC) {        // slot 0 == target
                float S = (tid < 64) ? g_ssum[2] / g_ssum[0] : g_ssum[3] / g_ssum[1];
                sh[tid] = fmaxf(fmaf(sWl1[tid], S, bl1[tid] + b1[tid]), 0.f);
            }
            __syncthreads();
            float acc = 0.f;
            const float* W = Wr2 + (q * 32) * HC + c;
            #pragma unroll
            for (int k = 0; k < 32; k++)
                acc = fmaf(sh[q * 32 + k], W[k * HC], acc);
            if (q > 0) sred[q - 1][c] = acc;
            __syncthreads();
            if (q == 0)
                g_xr2t[c] = acc + sred[0][c] + sred[1][c] + sred[2][c] + br2[c];
        }
    }

    // ---- arrive; block 0 waits for all, then conv2 + fc ----
    __syncthreads();
    if (tid == 0) { __threadfence(); atomicAdd(&g_bar3, 1); }
    if (bid != 0) return;
    if (tid == 0) {
        volatile int* v = &g_bar3;
        while (*v < TB) { }
        __threadfence();
    }
    __syncthreads();

    {
        int lane = tid & 31, w = tid >> 5;
        int c = tid & 127, q = tid >> 7;
        int tc = min(g_tcount, MAXTGT);
        int items = tc + 1;

        __shared__ float sxr[HC], sO[HC];
        __shared__ float sred2[3][HC];
        __shared__ int   snl[SCAP];
        __shared__ float2 slg[MAXTGT + 1];
        __shared__ float sal0[MAXTGT + 1], sal1[MAXTGT + 1];
        __shared__ int   sslot[MAXTGT + 1];
        __shared__ unsigned tmax0, tmax1;
        __shared__ float tsum0, tsum1;

        if (tid < HC) sxr[tid] = g_xr2t[tid];
        for (int j = tid; j < nn; j += TT) snl[j] = g_nodelist[j];
        if (tid == 0) { tmax0 = 0u; tmax1 = 0u; tsum0 = 0.f; tsum1 = 0.f; }
        __syncthreads();

        for (int i = w; i < items; i += 16) {
            int slot = 0; float a;
            if (i < tc) {
                int sn = g_tgt_src[i];
                for (int t = 0; t < nn; t++) { if (snl[t] == sn) { slot = t; break; } }
                a = g_tgt_a[i];
            } else { slot = 0; a = fill; }
            float p0 = 0.f, p1 = 0.f;
            #pragma unroll
            for (int k = 0; k < 4; k++) {
                int cc = lane + 32 * k;
                float vv = g_xl2[slot * HC + cc] + sxr[cc] + a * We2[cc];
                vv = lrelu(vv);
                float p = vv * att2[cc];
                if (k < 2) p0 += p; else p1 += p;
            }
            #pragma unroll
            for (int off = 16; off; off >>= 1) {
                p0 += __shfl_down_sync(0xffffffffu, p0, off);
                p1 += __shfl_down_sync(0xffffffffu, p1, off);
            }
            if (lane == 0) {
                slg[i] = make_float2(p0, p1);
                sslot[i] = slot;
                atomicMax(&tmax0, fenc(p0));
                atomicMax(&tmax1, fenc(p1));
            }
        }
        __syncthreads();
        float m0 = fdec(tmax0), m1 = fdec(tmax1);
        for (int i = tid; i < items; i += TT) {
            float2 l = slg[i];
            float e0 = expf(l.x - m0), e1 = expf(l.y - m1);
            sal0[i] = e0; sal1[i] = e1;
            atomicAdd(&tsum0, e0); atomicAdd(&tsum1, e1);
        }
        __syncthreads();

        float inv = (c < 64) ? (1.f / tsum0) : (1.f / tsum1);
        float agg = 0.f;
        for (int i = q; i < items; i += 4) {
            float al = ((c < 64) ? sal0[i] : sal1[i]) * inv;
            agg = fmaf(al, g_xl2[sslot[i] * HC + c], agg);
        }
        if (q > 0) sred2[q - 1][c] = agg;
        __syncthreads();
        if (q == 0) sO[c] = agg + sred2[0][c] + sred2[1][c] + sred2[2][c] + b2[c];
        __syncthreads();

        float r = 0.f;
        const float* Wf = Wfc + (q * 32) * HC + c;
        #pragma unroll
        for (int k = 0; k < 32; k++)
            r = fmaf(sO[q * 32 + k], Wf[k * HC], r);
        if (q > 0) sred2[q - 1][c] = r;
        __syncthreads();
        if (q == 0) out[c] = r + sred2[0][c] + sred2[1][c] + sred2[2][c] + bfc[c];
    }
}

// ---------------- launch ----------------
extern "C" void kernel_launch(void* const* d_in, const int* in_sizes, int n_in,
                              void* d_out, int out_size) {
    const float* x    = (const float*)d_in[0];
    const int*   ei   = (const int*)  d_in[1];
    const float* ea   = (const float*)d_in[2];
    const int*   tgtp = (const int*)  d_in[3];
    const float* Wl1  = (const float*)d_in[4];
    const float* bl1  = (const float*)d_in[5];
    const float* Wr1  = (const float*)d_in[6];
    const float* br1  = (const float*)d_in[7];
    const float* We1  = (const float*)d_in[8];
    const float* att1 = (const float*)d_in[9];
    const float* b1   = (const float*)d_in[10];
    const float* Wl2  = (const float*)d_in[11];
    const float* bl2  = (const float*)d_in[12];
    const float* Wr2  = (const float*)d_in[13];
    const float* br2  = (const float*)d_in[14];
    const float* We2  = (const float*)d_in[15];
    const float* att2 = (const float*)d_in[16];
    const float* b2   = (const float*)d_in[17];
    const float* Wfc  = (const float*)d_in[18];
    const float* bfc  = (const float*)d_in[19];
    float* out = (float*)d_out;

    int E = in_sizes[1] / 2;
    const int* src = ei;
    const int* dst = ei + E;

    k_reset<<<64, 256>>>(tgtp, Wl2, Wr2, Wfc);
    k_scan1<<<592, 256>>>(src, dst, ea, tgtp, E);
    k_scan2<<<592, 256>>>(src, dst, ea, x, E);
    k_tail<<<TB, TT>>>(x, Wl1, bl1, Wr1, br1, We1, att1, b1,
                       Wl2, bl2, Wr2, br2, We2, att2, b2, Wfc, bfc, out);
    (void)n_in; (void)out_size;
}

// round 8
// speedup vs baseline: 1.3938x; 1.1313x over previous
#include <cuda_runtime.h>

#define NN       50000
#define HC       128
#define NEG      0.2f
#define SCAP     256
#define MAXTGT   1024
#define LCAP     32768
#define BMWORDS  ((NN + 31) / 32)
#define TB       64               // tail blocks
#define TT       512              // tail threads/block

// ---------------- device scratch ----------------
__device__ unsigned g_bitmap[BMWORDS];
__device__ int      g_nodelist[SCAP];
__device__ int      g_tgt_src[MAXTGT];
__device__ float    g_tgt_a[MAXTGT];
__device__ int      g_Lslot[LCAP];
__device__ float    g_Lxs[LCAP];
__device__ float    g_La[LCAP];
__device__ float    g_ssum[4 * SCAP];
__device__ float    g_xl2[SCAP * HC];
__device__ float    g_xr2t[HC];
__device__ int      g_tcount, g_nnodes, g_lcount;
__device__ double   g_easum;
__device__ float    g_fill;
__device__ float    g_sink;
__device__ int      g_bar1, g_bar3;

__device__ __forceinline__ float lrelu(float v) { return v > 0.f ? v : NEG * v; }

__device__ __forceinline__ void grid_barrier(int* ctr) {
    __syncthreads();
    if (threadIdx.x == 0) {
        __threadfence();
        atomicAdd(ctr, 1);
        volatile int* v = ctr;
        while (*v < TB) { }
        __threadfence();
    }
    __syncthreads();
}

// ---------------- K0: reset + L2 weight prefetch ----------------
__global__ void k_reset(const int* tgtp,
                        const float* __restrict__ Wl2, const float* __restrict__ Wr2,
                        const float* __restrict__ Wfc) {
    int tid = threadIdx.x;
    if (blockIdx.x < 8) {
        int tgt = *tgtp;
        int i = blockIdx.x * blockDim.x + tid;
        int stride = 8 * blockDim.x;
        int tw = tgt >> 5;
        for (int j = i; j < BMWORDS; j += stride)
            g_bitmap[j] = (j == tw) ? (1u << (tgt & 31)) : 0u;
        for (int j = i; j < 4 * SCAP; j += stride) g_ssum[j] = 0.f;
        if (i == 0) {
            g_tcount = 0; g_nnodes = 1; g_lcount = 0; g_easum = 0.0;
            g_nodelist[0] = tgt;
            g_bar1 = 0; g_bar3 = 0;
        }
    } else {
        // pull Wl2/Wr2/Wfc into L2 while scans run
        int b = blockIdx.x - 8;               // 0..55
        const float* W = (b % 3 == 0) ? Wl2 : (b % 3 == 1) ? Wr2 : Wfc;
        int nb = 56 / 3, sub = b / 3;
        const float4* W4 = (const float4*)W;
        float acc = 0.f;
        int nv = (HC * HC) / 4;
        for (int j = sub * blockDim.x + tid; j < nv; j += nb * blockDim.x) {
            float4 v = W4[j];
            acc += v.x + v.y + v.z + v.w;
        }
        if (acc == 123456789.0f) g_sink = acc;
    }
}

// ---------------- K1: scan edges: ea mean + target in-edges + flag sources ----------------
__global__ void k_scan1(const int* __restrict__ src, const int* __restrict__ dst,
                        const float* __restrict__ ea, const int* tgtp, int E) {
    int tgt = *tgtp;
    int i = blockIdx.x * blockDim.x + threadIdx.x;
    int stride = gridDim.x * blockDim.x;
    int nv = E >> 2;
    const int4* d4 = (const int4*)dst;
    const float4* a4 = (const float4*)ea;
    double ax = 0.0, ay = 0.0, az = 0.0, aw = 0.0;   // 4 independent chains
    for (int v = i; v < nv; v += stride) {
        int4 d = d4[v];
        float4 a = a4[v];
        ax += (double)a.x; ay += (double)a.y; az += (double)a.z; aw += (double)a.w;
        int e = v << 2;
        #pragma unroll
        for (int c = 0; c < 4; c++) {
            int dd = (c == 0) ? d.x : (c == 1) ? d.y : (c == 2) ? d.z : d.w;
            if (dd == tgt) {
                float aa = (c == 0) ? a.x : (c == 1) ? a.y : (c == 2) ? a.z : a.w;
                int idx = atomicAdd(&g_tcount, 1);
                int s = src[e + c];
                if (idx < MAXTGT) { g_tgt_src[idx] = s; g_tgt_a[idx] = aa; }
                unsigned m = 1u << (s & 31);
                unsigned old = atomicOr(&g_bitmap[s >> 5], m);
                if (!(old & m)) {
                    int sl = atomicAdd(&g_nnodes, 1);
                    if (sl < SCAP) g_nodelist[sl] = s;
                }
            }
        }
    }
    for (int e = (nv << 2) + i; e < E; e += stride) {
        ax += (double)ea[e];
        if (dst[e] == tgt) {
            int idx = atomicAdd(&g_tcount, 1);
            int s = src[e];
            if (idx < MAXTGT) { g_tgt_src[idx] = s; g_tgt_a[idx] = ea[e]; }
            unsigned m = 1u << (s & 31);
            unsigned old = atomicOr(&g_bitmap[s >> 5], m);
            if (!(old & m)) {
                int sl = atomicAdd(&g_nnodes, 1);
                if (sl < SCAP) g_nodelist[sl] = s;
            }
        }
    }
    __shared__ double sd[256];
    sd[threadIdx.x] = (ax + ay) + (az + aw); __syncthreads();
    for (int off = blockDim.x >> 1; off; off >>= 1) {
        if (threadIdx.x < off) sd[threadIdx.x] += sd[threadIdx.x + off];
        __syncthreads();
    }
    if (threadIdx.x == 0) atomicAdd(&g_easum, sd[0]);
}

// ---------------- K2: collect edges into flagged nodes (shared bitmap) ----------------
__global__ void k_scan2(const int* __restrict__ src, const int* __restrict__ dst,
                        const float* __restrict__ ea, const float* __restrict__ x, int E) {
    __shared__ unsigned sbm[BMWORDS];
    __shared__ int snl[SCAP];
    __shared__ int snn;
    int tid = threadIdx.x;
    int i = blockIdx.x * blockDim.x + tid;
    if (i == 0) g_fill = (float)(g_easum / (double)E);
    int stride = gridDim.x * blockDim.x;

    for (int j = tid; j < BMWORDS; j += blockDim.x) sbm[j] = g_bitmap[j];
    if (tid == 0) snn = min(g_nnodes, SCAP);
    __syncthreads();
    int nn = snn;
    for (int j = tid; j < nn; j += blockDim.x) snl[j] = g_nodelist[j];
    __syncthreads();

    int nv = E >> 2;
    const int4* d4 = (const int4*)dst;
    for (int v = i; v < nv; v += stride) {
        int4 d = d4[v];
        int e = v << 2;
        #pragma unroll
        for (int c = 0; c < 4; c++) {
            int dd = (c == 0) ? d.x : (c == 1) ? d.y : (c == 2) ? d.z : d.w;
            if ((sbm[dd >> 5] >> (dd & 31)) & 1u) {
                int slot = 0;
                for (int t = 0; t < nn; t++) { if (snl[t] == dd) { slot = t; break; } }
                int idx = atomicAdd(&g_lcount, 1);
                if (idx < LCAP) {
                    g_Lslot[idx] = slot;
                    g_Lxs[idx]   = x[src[e + c]];
                    g_La[idx]    = ea[e + c];
                }
            }
        }
    }
    for (int e = (nv << 2) + i; e < E; e += stride) {
        int dd = dst[e];
        if ((sbm[dd >> 5] >> (dd & 31)) & 1u) {
            int slot = 0;
            for (int t = 0; t < nn; t++) { if (snl[t] == dd) { slot = t; break; } }
            int idx = atomicAdd(&g_lcount, 1);
            if (idx < LCAP) {
                g_Lslot[idx] = slot; g_Lxs[idx] = x[src[e]]; g_La[idx] = ea[e];
            }
        }
    }
}

// ---------------- K3: fused tail (no-max softmax) — stats + gemm + conv2/fc ----------------
__global__ void __launch_bounds__(TT) k_tail(
        const float* __restrict__ x,
        const float* __restrict__ Wl1, const float* __restrict__ bl1,
        const float* __restrict__ Wr1, const float* __restrict__ br1,
        const float* __restrict__ We1, const float* __restrict__ att1,
        const float* __restrict__ b1,
        const float* __restrict__ Wl2, const float* __restrict__ bl2,
        const float* __restrict__ Wr2, const float* __restrict__ br2,
        const float* __restrict__ We2, const float* __restrict__ att2,
        const float* __restrict__ b2,
        const float* __restrict__ Wfc, const float* __restrict__ bfc,
        float* __restrict__ out) {
    int tid = threadIdx.x, bid = blockIdx.x;
    int gtid = bid * TT + tid;
    int nn = min(g_nnodes, SCAP);
    int lc = min(g_lcount, LCAP);
    int total = lc + nn;
    float fill = g_fill;

    __shared__ float sWl1[HC], sWr1[HC], sWe1[HC], sAtt1[HC], sBlr[HC];
    __shared__ float sxd[SCAP];
    if (tid < HC) {
        sWl1[tid] = Wl1[tid]; sWr1[tid] = Wr1[tid]; sWe1[tid] = We1[tid];
        sAtt1[tid] = att1[tid];
        sBlr[tid] = bl1[tid] + br1[tid];
    }
    for (int j = tid; j < nn; j += TT) sxd[j] = x[g_nodelist[j]];
    __syncthreads();

    // ---- phase 1: single pass — logit, exp (no max), per-slot sums ----
    for (int i = gtid; i < total; i += TB * TT) {
        int slot; float xs, a;
        if (i < lc) { slot = g_Lslot[i]; xs = g_Lxs[i]; a = g_La[i]; }
        else        { slot = i - lc;     xs = sxd[slot]; a = fill; }
        float xd = sxd[slot];
        float p0 = 0.f, p1 = 0.f;
        #pragma unroll 8
        for (int j = 0; j < HC; j++) {
            float v = fmaf(xs, sWl1[j], fmaf(a, sWe1[j], fmaf(xd, sWr1[j], sBlr[j])));
            v = lrelu(v);
            float p = v * sAtt1[j];
            if (j < 64) p0 += p; else p1 += p;
        }
        float e0 = expf(p0), e1 = expf(p1);      // logits bounded; no overflow
        atomicAdd(&g_ssum[4 * slot],     e0);
        atomicAdd(&g_ssum[4 * slot + 1], e1);
        atomicAdd(&g_ssum[4 * slot + 2], e0 * xs);
        atomicAdd(&g_ssum[4 * slot + 3], e1 * xs);
    }
    grid_barrier(&g_bar1);

    // ---- phase 2: gemm per slot (blocks 0..62), xr2t (block 63) ----
    {
        int c = tid & 127, q = tid >> 7;
        __shared__ float sh[HC];
        __shared__ float sred[3][HC];
        if (bid < TB - 1) {
            for (int s = bid; s < nn; s += TB - 1) {
                if (tid < HC) {
                    float S = (tid < 64) ? g_ssum[4 * s + 2] / g_ssum[4 * s]
                                         : g_ssum[4 * s + 3] / g_ssum[4 * s + 1];
                    sh[tid] = fmaxf(fmaf(sWl1[tid], S, bl1[tid] + b1[tid]), 0.f);
                }
                __syncthreads();
                float acc = 0.f;
                const float* W = Wl2 + (q * 32) * HC + c;
                #pragma unroll
                for (int k = 0; k < 32; k++)
                    acc = fmaf(sh[q * 32 + k], W[k * HC], acc);
                if (q > 0) sred[q - 1][c] = acc;
                __syncthreads();
                if (q == 0)
                    g_xl2[s * HC + c] = acc + sred[0][c] + sred[1][c] + sred[2][c] + bl2[c];
                __syncthreads();
            }
        } else {
            if (tid < HC) {        // slot 0 == target
                float S = (tid < 64) ? g_ssum[2] / g_ssum[0] : g_ssum[3] / g_ssum[1];
                sh[tid] = fmaxf(fmaf(sWl1[tid], S, bl1[tid] + b1[tid]), 0.f);
            }
            __syncthreads();
            float acc = 0.f;
            const float* W = Wr2 + (q * 32) * HC + c;
            #pragma unroll
            for (int k = 0; k < 32; k++)
                acc = fmaf(sh[q * 32 + k], W[k * HC], acc);
            if (q > 0) sred[q - 1][c] = acc;
            __syncthreads();
            if (q == 0)
                g_xr2t[c] = acc + sred[0][c] + sred[1][c] + sred[2][c] + br2[c];
        }
    }

    // ---- arrive; block 0 waits for all, then conv2 + fc (no-max softmax) ----
    __syncthreads();
    if (tid == 0) { __threadfence(); atomicAdd(&g_bar3, 1); }
    if (bid != 0) return;
    if (tid == 0) {
        volatile int* v = &g_bar3;
        while (*v < TB) { }
        __threadfence();
    }
    __syncthreads();

    {
        int lane = tid & 31, w = tid >> 5;
        int c = tid & 127, q = tid >> 7;
        int tc = min(g_tcount, MAXTGT);
        int items = tc + 1;

        __shared__ float sxr[HC], sO[HC];
        __shared__ float sred2[3][HC];
        __shared__ int   snl[SCAP];
        __shared__ float sal0[MAXTGT + 1], sal1[MAXTGT + 1];
        __shared__ int   sslot[MAXTGT + 1];
        __shared__ float tsum0, tsum1;

        if (tid < HC) sxr[tid] = g_xr2t[tid];
        for (int j = tid; j < nn; j += TT) snl[j] = g_nodelist[j];
        if (tid == 0) { tsum0 = 0.f; tsum1 = 0.f; }
        __syncthreads();

        for (int i = w; i < items; i += 16) {
            int slot = 0; float a;
            if (i < tc) {
                int sn = g_tgt_src[i];
                for (int t = 0; t < nn; t++) { if (snl[t] == sn) { slot = t; break; } }
                a = g_tgt_a[i];
            } else { slot = 0; a = fill; }
            float p0 = 0.f, p1 = 0.f;
            #pragma unroll
            for (int k = 0; k < 4; k++) {
                int cc = lane + 32 * k;
                float vv = g_xl2[slot * HC + cc] + sxr[cc] + a * We2[cc];
                vv = lrelu(vv);
                float p = vv * att2[cc];
                if (k < 2) p0 += p; else p1 += p;
            }
            #pragma unroll
            for (int off = 16; off; off >>= 1) {
                p0 += __shfl_down_sync(0xffffffffu, p0, off);
                p1 += __shfl_down_sync(0xffffffffu, p1, off);
            }
            if (lane == 0) {
                float e0 = expf(p0), e1 = expf(p1);
                sal0[i] = e0; sal1[i] = e1;
                sslot[i] = slot;
                atomicAdd(&tsum0, e0); atomicAdd(&tsum1, e1);
            }
        }
        __syncthreads();

        float inv = (c < 64) ? (1.f / tsum0) : (1.f / tsum1);
        float agg = 0.f;
        for (int i = q; i < items; i += 4) {
            float al = ((c < 64) ? sal0[i] : sal1[i]) * inv;
            agg = fmaf(al, g_xl2[sslot[i] * HC + c], agg);
        }
        if (q > 0) sred2[q - 1][c] = agg;
        __syncthreads();
        if (q == 0) sO[c] = agg + sred2[0][c] + sred2[1][c] + sred2[2][c] + b2[c];
        __syncthreads();

        float r = 0.f;
        const float* Wf = Wfc + (q * 32) * HC + c;
        #pragma unroll
        for (int k = 0; k < 32; k++)
            r = fmaf(sO[q * 32 + k], Wf[k * HC], r);
        if (q > 0) sred2[q - 1][c] = r;
        __syncthreads();
        if (q == 0) out[c] = r + sred2[0][c] + sred2[1][c] + sred2[2][c] + bfc[c];
    }
}

// ---------------- launch ----------------
extern "C" void kernel_launch(void* const* d_in, const int* in_sizes, int n_in,
                              void* d_out, int out_size) {
    const float* x    = (const float*)d_in[0];
    const int*   ei   = (const int*)  d_in[1];
    const float* ea   = (const float*)d_in[2];
    const int*   tgtp = (const int*)  d_in[3];
    const float* Wl1  = (const float*)d_in[4];
    const float* bl1  = (const float*)d_in[5];
    const float* Wr1  = (const float*)d_in[6];
    const float* br1  = (const float*)d_in[7];
    const float* We1  = (const float*)d_in[8];
    const float* att1 = (const float*)d_in[9];
    const float* b1   = (const float*)d_in[10];
    const float* Wl2  = (const float*)d_in[11];
    const float* bl2  = (const float*)d_in[12];
    const float* Wr2  = (const float*)d_in[13];
    const float* br2  = (const float*)d_in[14];
    const float* We2  = (const float*)d_in[15];
    const float* att2 = (const float*)d_in[16];
    const float* b2   = (const float*)d_in[17];
    const float* Wfc  = (const float*)d_in[18];
    const float* bfc  = (const float*)d_in[19];
    float* out = (float*)d_out;

    int E = in_sizes[1] / 2;
    const int* src = ei;
    const int* dst = ei + E;

    k_reset<<<64, 256>>>(tgtp, Wl2, Wr2, Wfc);
    k_scan1<<<592, 256>>>(src, dst, ea, tgtp, E);
    k_scan2<<<592, 256>>>(src, dst, ea, x, E);
    k_tail<<<TB, TT>>>(x, Wl1, bl1, Wr1, br1, We1, att1, b1,
                       Wl2, bl2, Wr2, br2, We2, att2, b2, Wfc, bfc, out);
    (void)n_in; (void)out_size;
}

// round 9
// speedup vs baseline: 1.4381x; 1.0317x over previous
#include <cuda_runtime.h>

#define NN       50000
#define HC       128
#define NEG      0.2f
#define SCAP     256
#define MAXTGT   1024
#define LCAP     32768
#define BMWORDS  ((NN + 31) / 32)

// ---------------- device scratch ----------------
__device__ unsigned g_bitmap[BMWORDS];
__device__ int      g_nodelist[SCAP];
__device__ int      g_tgt_src[MAXTGT];
__device__ float    g_tgt_a[MAXTGT];
__device__ int      g_Lslot[LCAP];
__device__ float    g_Lxs[LCAP];
__device__ float    g_La[LCAP];
__device__ float    g_h1[SCAP * HC];
__device__ float    g_xl2[SCAP * HC];
__device__ float    g_xr2t[HC];
__device__ int      g_tcount, g_nnodes, g_lcount;
__device__ double   g_easum;
__device__ float    g_fill;
__device__ float    g_sink;

__device__ __forceinline__ float lrelu(float v) { return v > 0.f ? v : NEG * v; }

// ---------------- K0: reset + L2 prefetch (weights + x) ----------------
__global__ void k_reset(const int* tgtp,
                        const float* __restrict__ Wl2, const float* __restrict__ Wr2,
                        const float* __restrict__ Wfc, const float* __restrict__ x,
                        const float* __restrict__ Wl1, const float* __restrict__ Wr1,
                        const float* __restrict__ We1, const float* __restrict__ att1,
                        const float* __restrict__ bl1, const float* __restrict__ br1,
                        const float* __restrict__ b1) {
    int tid = threadIdx.x;
    float acc = 0.f;
    if (blockIdx.x < 8) {
        int tgt = *tgtp;
        int i = blockIdx.x * blockDim.x + tid;
        int stride = 8 * blockDim.x;
        int tw = tgt >> 5;
        for (int j = i; j < BMWORDS; j += stride)
            g_bitmap[j] = (j == tw) ? (1u << (tgt & 31)) : 0u;
        if (i == 0) {
            g_tcount = 0; g_nnodes = 1; g_lcount = 0; g_easum = 0.0;
            g_nodelist[0] = tgt;
        }
        return;
    } else if (blockIdx.x < 56) {
        // Wl2/Wr2/Wfc -> L2
        int b = blockIdx.x - 8;               // 0..47
        const float* W = (b % 3 == 0) ? Wl2 : (b % 3 == 1) ? Wr2 : Wfc;
        int nb = 16, sub = b / 3;
        const float4* W4 = (const float4*)W;
        int nv = (HC * HC) / 4;
        for (int j = sub * blockDim.x + tid; j < nv; j += nb * blockDim.x) {
            float4 v = W4[j];
            acc += v.x + v.y + v.z + v.w;
        }
    } else if (blockIdx.x < 63) {
        // x (200 KB) -> L2
        int sub = blockIdx.x - 56;            // 0..6
        const float4* x4 = (const float4*)x;
        int nv = NN / 4;
        for (int j = sub * blockDim.x + tid; j < nv; j += 7 * blockDim.x) {
            float4 v = x4[j];
            acc += v.x + v.y + v.z + v.w;
        }
    } else {
        // conv1 weight group -> L2
        if (tid < HC)
            acc = Wl1[tid] + Wr1[tid] + We1[tid] + att1[tid]
                + bl1[tid] + br1[tid] + b1[tid];
    }
    if (acc == 123456789.0f) g_sink = acc;   // keep loads alive
}

// ---------------- K1: scan dst only: target in-edges + flag sources ----------------
__global__ void k_scan1(const int* __restrict__ src, const int* __restrict__ dst,
                        const float* __restrict__ ea, const int* tgtp, int E) {
    int tgt = *tgtp;
    int i = blockIdx.x * blockDim.x + threadIdx.x;
    int stride = gridDim.x * blockDim.x;
    int nv = E >> 2;
    const int4* d4 = (const int4*)dst;
    for (int v = i; v < nv; v += stride) {
        int4 d = d4[v];
        int e = v << 2;
        #pragma unroll
        for (int c = 0; c < 4; c++) {
            int dd = (c == 0) ? d.x : (c == 1) ? d.y : (c == 2) ? d.z : d.w;
            if (dd == tgt) {
                int idx = atomicAdd(&g_tcount, 1);
                int s = src[e + c];
                if (idx < MAXTGT) { g_tgt_src[idx] = s; g_tgt_a[idx] = ea[e + c]; }
                unsigned m = 1u << (s & 31);
                unsigned old = atomicOr(&g_bitmap[s >> 5], m);
                if (!(old & m)) {
                    int sl = atomicAdd(&g_nnodes, 1);
                    if (sl < SCAP) g_nodelist[sl] = s;
                }
            }
        }
    }
    for (int e = (nv << 2) + i; e < E; e += stride) {
        if (dst[e] == tgt) {
            int idx = atomicAdd(&g_tcount, 1);
            int s = src[e];
            if (idx < MAXTGT) { g_tgt_src[idx] = s; g_tgt_a[idx] = ea[e]; }
            unsigned m = 1u << (s & 31);
            unsigned old = atomicOr(&g_bitmap[s >> 5], m);
            if (!(old & m)) {
                int sl = atomicAdd(&g_nnodes, 1);
                if (sl < SCAP) g_nodelist[sl] = s;
            }
        }
    }
}

// ---------------- K2: collect edges into flagged nodes + ea sum ----------------
__global__ void k_scan2(const int* __restrict__ src, const int* __restrict__ dst,
                        const float* __restrict__ ea, const float* __restrict__ x, int E) {
    __shared__ unsigned sbm[BMWORDS];
    __shared__ int snl[SCAP];
    __shared__ int snn;
    int tid = threadIdx.x;
    int i = blockIdx.x * blockDim.x + tid;
    int stride = gridDim.x * blockDim.x;

    for (int j = tid; j < BMWORDS; j += blockDim.x) sbm[j] = g_bitmap[j];
    if (tid == 0) snn = min(g_nnodes, SCAP);
    __syncthreads();
    int nn = snn;
    for (int j = tid; j < nn; j += blockDim.x) snl[j] = g_nodelist[j];
    __syncthreads();

    int nv = E >> 2;
    const int4* d4 = (const int4*)dst;
    const float4* a4 = (const float4*)ea;
    float ax = 0.f, ay = 0.f, az = 0.f, aw = 0.f;
    for (int v = i; v < nv; v += stride) {
        int4 d = d4[v];
        float4 a = a4[v];
        ax += a.x; ay += a.y; az += a.z; aw += a.w;
        int e = v << 2;
        #pragma unroll
        for (int c = 0; c < 4; c++) {
            int dd = (c == 0) ? d.x : (c == 1) ? d.y : (c == 2) ? d.z : d.w;
            if ((sbm[dd >> 5] >> (dd & 31)) & 1u) {
                float aa = (c == 0) ? a.x : (c == 1) ? a.y : (c == 2) ? a.z : a.w;
                int slot = 0;
                for (int t = 0; t < nn; t++) { if (snl[t] == dd) { slot = t; break; } }
                int idx = atomicAdd(&g_lcount, 1);
                if (idx < LCAP) {
                    g_Lslot[idx] = slot;
                    g_Lxs[idx]   = x[src[e + c]];
                    g_La[idx]    = aa;
                }
            }
        }
    }
    for (int e = (nv << 2) + i; e < E; e += stride) {
        int dd = dst[e];
        ax += ea[e];
        if ((sbm[dd >> 5] >> (dd & 31)) & 1u) {
            int slot = 0;
            for (int t = 0; t < nn; t++) { if (snl[t] == dd) { slot = t; break; } }
            int idx = atomicAdd(&g_lcount, 1);
            if (idx < LCAP) {
                g_Lslot[idx] = slot; g_Lxs[idx] = x[src[e]]; g_La[idx] = ea[e];
            }
        }
    }
    __shared__ double sd[256];
    sd[tid] = (double)((ax + ay) + (az + aw)); __syncthreads();
    for (int off = blockDim.x >> 1; off; off >>= 1) {
        if (tid < off) sd[tid] += sd[tid + off];
        __syncthreads();
    }
    if (tid == 0) atomicAdd(&g_easum, sd[0]);
}

// ---------------- K3: conv1 stats — single pass, shared atomics, h1 emit ----------------
__global__ void __launch_bounds__(512) k_stats(
        const float* __restrict__ x,
        const float* __restrict__ Wl1, const float* __restrict__ bl1,
        const float* __restrict__ Wr1, const float* __restrict__ br1,
        const float* __restrict__ We1, const float* __restrict__ att1,
        const float* __restrict__ b1, int E) {
    int tid = threadIdx.x;
    int nn = min(g_nnodes, SCAP);
    int lc = min(g_lcount, LCAP);
    int total = lc + nn;

    __shared__ float sWl1[HC], sWr1[HC], sWe1[HC], sAtt1[HC], sBlr[HC];
    __shared__ float sxd[SCAP];
    __shared__ float ssum[4 * SCAP];
    __shared__ float sfill;

    if (tid < HC) {
        sWl1[tid] = Wl1[tid]; sWr1[tid] = Wr1[tid]; sWe1[tid] = We1[tid];
        sAtt1[tid] = att1[tid];
        sBlr[tid] = bl1[tid] + br1[tid];
    }
    for (int j = tid; j < nn; j += 512) sxd[j] = x[g_nodelist[j]];
    for (int j = tid; j < 4 * nn; j += 512) ssum[j] = 0.f;
    if (tid == 0) {
        float f = (float)(g_easum / (double)E);
        sfill = f; g_fill = f;
    }
    __syncthreads();
    float fill = sfill;

    // single pass: logit -> exp (no max; logits bounded) -> shared sums
    for (int i = tid; i < total; i += 512) {
        int slot; float xs, a;
        if (i < lc) { slot = g_Lslot[i]; xs = g_Lxs[i]; a = g_La[i]; }
        else        { slot = i - lc;     xs = sxd[slot]; a = fill; }
        float xd = sxd[slot];
        float p0 = 0.f, p1 = 0.f;
        #pragma unroll 8
        for (int j = 0; j < HC; j++) {
            float v = fmaf(xs, sWl1[j], fmaf(a, sWe1[j], fmaf(xd, sWr1[j], sBlr[j])));
            v = lrelu(v);
            float p = v * sAtt1[j];
            if (j < 64) p0 += p; else p1 += p;
        }
        float e0 = expf(p0), e1 = expf(p1);
        atomicAdd(&ssum[4 * slot],     e0);
        atomicAdd(&ssum[4 * slot + 1], e1);
        atomicAdd(&ssum[4 * slot + 2], e0 * xs);
        atomicAdd(&ssum[4 * slot + 3], e1 * xs);
    }
    __syncthreads();

    // h1[slot][c] = relu(Wl1[c] * S_head(c) + bl1[c] + b1[c])
    for (int idx = tid; idx < nn * HC; idx += 512) {
        int s = idx >> 7, c = idx & 127;
        float S = (c < 64) ? ssum[4 * s + 2] / ssum[4 * s]
                           : ssum[4 * s + 3] / ssum[4 * s + 1];
        g_h1[idx] = fmaxf(fmaf(sWl1[c], S, bl1[c] + b1[c]), 0.f);
    }
}

// ---------------- K4: parallel GEMM — xl2 (block per slot) + xr2t (block 63) ----------------
__global__ void __launch_bounds__(512) k_gemm(
        const float* __restrict__ Wl2, const float* __restrict__ bl2,
        const float* __restrict__ Wr2, const float* __restrict__ br2) {
    int tid = threadIdx.x, c = tid & 127, q = tid >> 7;
    int nn = min(g_nnodes, SCAP);
    __shared__ float sh[HC];
    __shared__ float sred[3][HC];

    if (blockIdx.x < 63) {
        for (int s = blockIdx.x; s < nn; s += 63) {
            if (tid < HC) sh[tid] = g_h1[s * HC + tid];
            __syncthreads();
            float acc = 0.f;
            const float* W = Wl2 + (q * 32) * HC + c;
            #pragma unroll
            for (int k = 0; k < 32; k++)
                acc = fmaf(sh[q * 32 + k], W[k * HC], acc);
            if (q > 0) sred[q - 1][c] = acc;
            __syncthreads();
            if (q == 0)
                g_xl2[s * HC + c] = acc + sred[0][c] + sred[1][c] + sred[2][c] + bl2[c];
            __syncthreads();
        }
    } else {
        if (tid < HC) sh[tid] = g_h1[tid];     // slot 0 == target
        __syncthreads();
        float acc = 0.f;
        const float* W = Wr2 + (q * 32) * HC + c;
        #pragma unroll
        for (int k = 0; k < 32; k++)
            acc = fmaf(sh[q * 32 + k], W[k * HC], acc);
        if (q > 0) sred[q - 1][c] = acc;
        __syncthreads();
        if (q == 0)
            g_xr2t[c] = acc + sred[0][c] + sred[1][c] + sred[2][c] + br2[c];
    }
}

// ---------------- K5: conv2 at target + fc (no-max softmax) ----------------
__global__ void __launch_bounds__(512) k_final(
        const float* __restrict__ We2, const float* __restrict__ att2,
        const float* __restrict__ b2,
        const float* __restrict__ Wfc, const float* __restrict__ bfc,
        float* __restrict__ out) {
    int tid = threadIdx.x, lane = tid & 31, w = tid >> 5;
    int c = tid & 127, q = tid >> 7;
    int nn = min(g_nnodes, SCAP);
    int tc = min(g_tcount, MAXTGT);
    int items = tc + 1;
    float fill = g_fill;

    __shared__ float sxr[HC], sO[HC];
    __shared__ float sred2[3][HC];
    __shared__ int   snl[SCAP];
    __shared__ float sal0[MAXTGT + 1], sal1[MAXTGT + 1];
    __shared__ int   sslot[MAXTGT + 1];
    __shared__ float tsum0, tsum1;

    if (tid < HC) sxr[tid] = g_xr2t[tid];
    for (int j = tid; j < nn; j += 512) snl[j] = g_nodelist[j];
    if (tid == 0) { tsum0 = 0.f; tsum1 = 0.f; }
    __syncthreads();

    for (int i = w; i < items; i += 16) {
        int slot = 0; float a;
        if (i < tc) {
            int sn = g_tgt_src[i];
            for (int t = 0; t < nn; t++) { if (snl[t] == sn) { slot = t; break; } }
            a = g_tgt_a[i];
        } else { slot = 0; a = fill; }
        float p0 = 0.f, p1 = 0.f;
        #pragma unroll
        for (int k = 0; k < 4; k++) {
            int cc = lane + 32 * k;
            float vv = g_xl2[slot * HC + cc] + sxr[cc] + a * We2[cc];
            vv = lrelu(vv);
            float p = vv * att2[cc];
            if (k < 2) p0 += p; else p1 += p;
        }
        #pragma unroll
        for (int off = 16; off; off >>= 1) {
            p0 += __shfl_down_sync(0xffffffffu, p0, off);
            p1 += __shfl_down_sync(0xffffffffu, p1, off);
        }
        if (lane == 0) {
            float e0 = expf(p0), e1 = expf(p1);
            sal0[i] = e0; sal1[i] = e1;
            sslot[i] = slot;
            atomicAdd(&tsum0, e0); atomicAdd(&tsum1, e1);
        }
    }
    __syncthreads();

    float inv = (c < 64) ? (1.f / tsum0) : (1.f / tsum1);
    float agg = 0.f;
    for (int i = q; i < items; i += 4) {
        float al = ((c < 64) ? sal0[i] : sal1[i]) * inv;
        agg = fmaf(al, g_xl2[sslot[i] * HC + c], agg);
    }
    if (q > 0) sred2[q - 1][c] = agg;
    __syncthreads();
    if (q == 0) sO[c] = agg + sred2[0][c] + sred2[1][c] + sred2[2][c] + b2[c];
    __syncthreads();

    float r = 0.f;
    const float* Wf = Wfc + (q * 32) * HC + c;
    #pragma unroll
    for (int k = 0; k < 32; k++)
        r = fmaf(sO[q * 32 + k], Wf[k * HC], r);
    if (q > 0) sred2[q - 1][c] = r;
    __syncthreads();
    if (q == 0) out[c] = r + sred2[0][c] + sred2[1][c] + sred2[2][c] + bfc[c];
}

// ---------------- launch ----------------
extern "C" void kernel_launch(void* const* d_in, const int* in_sizes, int n_in,
                              void* d_out, int out_size) {
    const float* x    = (const float*)d_in[0];
    const int*   ei   = (const int*)  d_in[1];
    const float* ea   = (const float*)d_in[2];
    const int*   tgtp = (const int*)  d_in[3];
    const float* Wl1  = (const float*)d_in[4];
    const float* bl1  = (const float*)d_in[5];
    const float* Wr1  = (const float*)d_in[6];
    const float* br1  = (const float*)d_in[7];
    const float* We1  = (const float*)d_in[8];
    const float* att1 = (const float*)d_in[9];
    const float* b1   = (const float*)d_in[10];
    const float* Wl2  = (const float*)d_in[11];
    const float* bl2  = (const float*)d_in[12];
    const float* Wr2  = (const float*)d_in[13];
    const float* br2  = (const float*)d_in[14];
    const float* We2  = (const float*)d_in[15];
    const float* att2 = (const float*)d_in[16];
    const float* b2   = (const float*)d_in[17];
    const float* Wfc  = (const float*)d_in[18];
    const float* bfc  = (const float*)d_in[19];
    float* out = (float*)d_out;

    int E = in_sizes[1] / 2;
    const int* src = ei;
    const int* dst = ei + E;

    k_reset<<<64, 256>>>(tgtp, Wl2, Wr2, Wfc, x, Wl1, Wr1, We1, att1, bl1, br1, b1);
    k_scan1<<<592, 256>>>(src, dst, ea, tgtp, E);
    k_scan2<<<592, 256>>>(src, dst, ea, x, E);
    k_stats<<<1, 512>>>(x, Wl1, bl1, Wr1, br1, We1, att1, b1, E);
    k_gemm <<<64, 512>>>(Wl2, bl2, Wr2, br2);
    k_final<<<1, 512>>>(We2, att2, b2, Wfc, bfc, out);
    (void)n_in; (void)out_size;
}

// round 10
// speedup vs baseline: 1.6045x; 1.1157x over previous
#include <cuda_runtime.h>

#define NN       50000
#define HC       128
#define NEG      0.2f
#define SCAP     256
#define MAXTGT   1024
#define LCAP     32768
#define BMWORDS  ((NN + 31) / 32)
#define STB      64                // stats blocks

// ---------------- device scratch ----------------
__device__ unsigned g_bitmap[BMWORDS];
__device__ int      g_nodelist[SCAP];
__device__ int      g_tgt_src[MAXTGT];
__device__ float    g_tgt_a[MAXTGT];
__device__ int      g_Lslot[LCAP];
__device__ float    g_Lxs[LCAP];
__device__ float    g_La[LCAP];
__device__ float    g_ssum[4 * SCAP];
__device__ float    g_xl2[SCAP * HC];
__device__ float    g_xr2t[HC];
__device__ int      g_tcount, g_nnodes, g_lcount;
__device__ double   g_easum;
__device__ float    g_fill;
__device__ float    g_sink;

__device__ __forceinline__ float lrelu(float v) { return v > 0.f ? v : NEG * v; }

// ---------------- K0: reset + L2 prefetch (weights + x) ----------------
__global__ void k_reset(const int* tgtp,
                        const float* __restrict__ Wl2, const float* __restrict__ Wr2,
                        const float* __restrict__ Wfc, const float* __restrict__ x,
                        const float* __restrict__ Wl1, const float* __restrict__ Wr1,
                        const float* __restrict__ We1, const float* __restrict__ att1,
                        const float* __restrict__ bl1, const float* __restrict__ br1,
                        const float* __restrict__ b1) {
    int tid = threadIdx.x;
    float acc = 0.f;
    if (blockIdx.x < 8) {
        int tgt = *tgtp;
        int i = blockIdx.x * blockDim.x + tid;
        int stride = 8 * blockDim.x;
        int tw = tgt >> 5;
        for (int j = i; j < BMWORDS; j += stride)
            g_bitmap[j] = (j == tw) ? (1u << (tgt & 31)) : 0u;
        for (int j = i; j < 4 * SCAP; j += stride) g_ssum[j] = 0.f;
        if (i == 0) {
            g_tcount = 0; g_nnodes = 1; g_lcount = 0; g_easum = 0.0;
            g_nodelist[0] = tgt;
        }
        return;
    } else if (blockIdx.x < 56) {
        // Wl2/Wr2/Wfc -> L2
        int b = blockIdx.x - 8;
        const float* W = (b % 3 == 0) ? Wl2 : (b % 3 == 1) ? Wr2 : Wfc;
        int nb = 16, sub = b / 3;
        const float4* W4 = (const float4*)W;
        int nv = (HC * HC) / 4;
        for (int j = sub * blockDim.x + tid; j < nv; j += nb * blockDim.x) {
            float4 v = W4[j];
            acc += v.x + v.y + v.z + v.w;
        }
    } else if (blockIdx.x < 63) {
        // x (200 KB) -> L2
        int sub = blockIdx.x - 56;
        const float4* x4 = (const float4*)x;
        int nv = NN / 4;
        for (int j = sub * blockDim.x + tid; j < nv; j += 7 * blockDim.x) {
            float4 v = x4[j];
            acc += v.x + v.y + v.z + v.w;
        }
    } else {
        // conv1 weight group -> L2
        if (tid < HC)
            acc = Wl1[tid] + Wr1[tid] + We1[tid] + att1[tid]
                + bl1[tid] + br1[tid] + b1[tid];
    }
    if (acc == 123456789.0f) g_sink = acc;
}

// ---------------- K1: scan dst only: target in-edges + flag sources ----------------
__global__ void k_scan1(const int* __restrict__ src, const int* __restrict__ dst,
                        const float* __restrict__ ea, const int* tgtp, int E) {
    int tgt = *tgtp;
    int i = blockIdx.x * blockDim.x + threadIdx.x;
    int stride = gridDim.x * blockDim.x;
    int nv = E >> 2;
    const int4* d4 = (const int4*)dst;
    for (int v = i; v < nv; v += stride) {
        int4 d = d4[v];
        int e = v << 2;
        #pragma unroll
        for (int c = 0; c < 4; c++) {
            int dd = (c == 0) ? d.x : (c == 1) ? d.y : (c == 2) ? d.z : d.w;
            if (dd == tgt) {
                int idx = atomicAdd(&g_tcount, 1);
                int s = src[e + c];
                if (idx < MAXTGT) { g_tgt_src[idx] = s; g_tgt_a[idx] = ea[e + c]; }
                unsigned m = 1u << (s & 31);
                unsigned old = atomicOr(&g_bitmap[s >> 5], m);
                if (!(old & m)) {
                    int sl = atomicAdd(&g_nnodes, 1);
                    if (sl < SCAP) g_nodelist[sl] = s;
                }
            }
        }
    }
    for (int e = (nv << 2) + i; e < E; e += stride) {
        if (dst[e] == tgt) {
            int idx = atomicAdd(&g_tcount, 1);
            int s = src[e];
            if (idx < MAXTGT) { g_tgt_src[idx] = s; g_tgt_a[idx] = ea[e]; }
            unsigned m = 1u << (s & 31);
            unsigned old = atomicOr(&g_bitmap[s >> 5], m);
            if (!(old & m)) {
                int sl = atomicAdd(&g_nnodes, 1);
                if (sl < SCAP) g_nodelist[sl] = s;
            }
        }
    }
}

// ---------------- K2: collect edges into flagged nodes + ea sum ----------------
__global__ void k_scan2(const int* __restrict__ src, const int* __restrict__ dst,
                        const float* __restrict__ ea, const float* __restrict__ x, int E) {
    __shared__ unsigned sbm[BMWORDS];
    __shared__ int snl[SCAP];
    __shared__ int snn;
    int tid = threadIdx.x;
    int i = blockIdx.x * blockDim.x + tid;
    int stride = gridDim.x * blockDim.x;

    for (int j = tid; j < BMWORDS; j += blockDim.x) sbm[j] = g_bitmap[j];
    if (tid == 0) snn = min(g_nnodes, SCAP);
    __syncthreads();
    int nn = snn;
    for (int j = tid; j < nn; j += blockDim.x) snl[j] = g_nodelist[j];
    __syncthreads();

    int nv = E >> 2;
    const int4* d4 = (const int4*)dst;
    const float4* a4 = (const float4*)ea;
    float ax = 0.f, ay = 0.f, az = 0.f, aw = 0.f;
    for (int v = i; v < nv; v += stride) {
        int4 d = d4[v];
        float4 a = a4[v];
        ax += a.x; ay += a.y; az += a.z; aw += a.w;
        int e = v << 2;
        #pragma unroll
        for (int c = 0; c < 4; c++) {
            int dd = (c == 0) ? d.x : (c == 1) ? d.y : (c == 2) ? d.z : d.w;
            if ((sbm[dd >> 5] >> (dd & 31)) & 1u) {
                float aa = (c == 0) ? a.x : (c == 1) ? a.y : (c == 2) ? a.z : a.w;
                int slot = 0;
                for (int t = 0; t < nn; t++) { if (snl[t] == dd) { slot = t; break; } }
                int idx = atomicAdd(&g_lcount, 1);
                if (idx < LCAP) {
                    g_Lslot[idx] = slot;
                    g_Lxs[idx]   = x[src[e + c]];
                    g_La[idx]    = aa;
                }
            }
        }
    }
    for (int e = (nv << 2) + i; e < E; e += stride) {
        int dd = dst[e];
        ax += ea[e];
        if ((sbm[dd >> 5] >> (dd & 31)) & 1u) {
            int slot = 0;
            for (int t = 0; t < nn; t++) { if (snl[t] == dd) { slot = t; break; } }
            int idx = atomicAdd(&g_lcount, 1);
            if (idx < LCAP) {
                g_Lslot[idx] = slot; g_Lxs[idx] = x[src[e]]; g_La[idx] = ea[e];
            }
        }
    }
    __shared__ double sd[256];
    sd[tid] = (double)((ax + ay) + (az + aw)); __syncthreads();
    for (int off = blockDim.x >> 1; off; off >>= 1) {
        if (tid < off) sd[tid] += sd[tid + off];
        __syncthreads();
    }
    if (tid == 0) atomicAdd(&g_easum, sd[0]);
}

// ---------------- K3: conv1 stats — MULTI-BLOCK, global atomic sums ----------------
__global__ void __launch_bounds__(256) k_stats(
        const float* __restrict__ x,
        const float* __restrict__ Wl1, const float* __restrict__ bl1,
        const float* __restrict__ Wr1, const float* __restrict__ br1,
        const float* __restrict__ We1, const float* __restrict__ att1, int E) {
    int tid = threadIdx.x, bid = blockIdx.x;
    int nn = min(g_nnodes, SCAP);
    int lc = min(g_lcount, LCAP);
    int total = lc + nn;
    float fill = (float)(g_easum / (double)E);
    if (bid == 0 && tid == 0) g_fill = fill;

    __shared__ float sWl1[HC], sWr1[HC], sWe1[HC], sAtt1[HC], sBlr[HC];
    __shared__ float sxd[SCAP];
    if (tid < HC) {
        sWl1[tid] = Wl1[tid]; sWr1[tid] = Wr1[tid]; sWe1[tid] = We1[tid];
        sAtt1[tid] = att1[tid];
        sBlr[tid] = bl1[tid] + br1[tid];
    }
    for (int j = tid; j < nn; j += 256) sxd[j] = x[g_nodelist[j]];
    __syncthreads();

    // block-cyclic item distribution: ~total/STB items per block, in parallel lanes
    for (int i = bid + STB * tid; i < total; i += STB * 256) {
        int slot; float xs, a;
        if (i < lc) { slot = g_Lslot[i]; xs = g_Lxs[i]; a = g_La[i]; }
        else        { slot = i - lc;     xs = sxd[slot]; a = fill; }
        float xd = sxd[slot];
        float p0 = 0.f, p1 = 0.f;
        #pragma unroll 8
        for (int j = 0; j < HC; j++) {
            float v = fmaf(xs, sWl1[j], fmaf(a, sWe1[j], fmaf(xd, sWr1[j], sBlr[j])));
            v = lrelu(v);
            float p = v * sAtt1[j];
            if (j < 64) p0 += p; else p1 += p;
        }
        float e0 = expf(p0), e1 = expf(p1);     // logits bounded; no max needed
        atomicAdd(&g_ssum[4 * slot],     e0);
        atomicAdd(&g_ssum[4 * slot + 1], e1);
        atomicAdd(&g_ssum[4 * slot + 2], e0 * xs);
        atomicAdd(&g_ssum[4 * slot + 3], e1 * xs);
    }
}

// ---------------- K4: parallel GEMM — h1 in-block; xl2 per slot + xr2t (block 63) ----
__global__ void __launch_bounds__(512) k_gemm(
        const float* __restrict__ Wl1, const float* __restrict__ bl1,
        const float* __restrict__ b1,
        const float* __restrict__ Wl2, const float* __restrict__ bl2,
        const float* __restrict__ Wr2, const float* __restrict__ br2) {
    int tid = threadIdx.x, c = tid & 127, q = tid >> 7;
    int nn = min(g_nnodes, SCAP);
    __shared__ float sh[HC];
    __shared__ float sred[3][HC];

    if (blockIdx.x < 63) {
        for (int s = blockIdx.x; s < nn; s += 63) {
            if (tid < HC) {
                float S = (tid < 64) ? g_ssum[4 * s + 2] / g_ssum[4 * s]
                                     : g_ssum[4 * s + 3] / g_ssum[4 * s + 1];
                sh[tid] = fmaxf(fmaf(Wl1[tid], S, bl1[tid] + b1[tid]), 0.f);
            }
            __syncthreads();
            float acc = 0.f;
            const float* W = Wl2 + (q * 32) * HC + c;
            #pragma unroll
            for (int k = 0; k < 32; k++)
                acc = fmaf(sh[q * 32 + k], W[k * HC], acc);
            if (q > 0) sred[q - 1][c] = acc;
            __syncthreads();
            if (q == 0)
                g_xl2[s * HC + c] = acc + sred[0][c] + sred[1][c] + sred[2][c] + bl2[c];
            __syncthreads();
        }
    } else {
        if (tid < HC) {            // slot 0 == target
            float S = (tid < 64) ? g_ssum[2] / g_ssum[0] : g_ssum[3] / g_ssum[1];
            sh[tid] = fmaxf(fmaf(Wl1[tid], S, bl1[tid] + b1[tid]), 0.f);
        }
        __syncthreads();
        float acc = 0.f;
        const float* W = Wr2 + (q * 32) * HC + c;
        #pragma unroll
        for (int k = 0; k < 32; k++)
            acc = fmaf(sh[q * 32 + k], W[k * HC], acc);
        if (q > 0) sred[q - 1][c] = acc;
        __syncthreads();
        if (q == 0)
            g_xr2t[c] = acc + sred[0][c] + sred[1][c] + sred[2][c] + br2[c];
    }
}

// ---------------- K5: conv2 at target + fc (no-max softmax) ----------------
__global__ void __launch_bounds__(512) k_final(
        const float* __restrict__ We2, const float* __restrict__ att2,
        const float* __restrict__ b2,
        const float* __restrict__ Wfc, const float* __restrict__ bfc,
        float* __restrict__ out) {
    int tid = threadIdx.x, lane = tid & 31, w = tid >> 5;
    int c = tid & 127, q = tid >> 7;
    int nn = min(g_nnodes, SCAP);
    int tc = min(g_tcount, MAXTGT);
    int items = tc + 1;
    float fill = g_fill;

    __shared__ float sxr[HC], sO[HC];
    __shared__ float sred2[3][HC];
    __shared__ int   snl[SCAP];
    __shared__ float sal0[MAXTGT + 1], sal1[MAXTGT + 1];
    __shared__ int   sslot[MAXTGT + 1];
    __shared__ float tsum0, tsum1;

    if (tid < HC) sxr[tid] = g_xr2t[tid];
    for (int j = tid; j < nn; j += 512) snl[j] = g_nodelist[j];
    if (tid == 0) { tsum0 = 0.f; tsum1 = 0.f; }
    __syncthreads();

    for (int i = w; i < items; i += 16) {
        int slot = 0; float a;
        if (i < tc) {
            int sn = g_tgt_src[i];
            for (int t = 0; t < nn; t++) { if (snl[t] == sn) { slot = t; break; } }
            a = g_tgt_a[i];
        } else { slot = 0; a = fill; }
        float p0 = 0.f, p1 = 0.f;
        #pragma unroll
        for (int k = 0; k < 4; k++) {
            int cc = lane + 32 * k;
            float vv = g_xl2[slot * HC + cc] + sxr[cc] + a * We2[cc];
            vv = lrelu(vv);
            float p = vv * att2[cc];
            if (k < 2) p0 += p; else p1 += p;
        }
        #pragma unroll
        for (int off = 16; off; off >>= 1) {
            p0 += __shfl_down_sync(0xffffffffu, p0, off);
            p1 += __shfl_down_sync(0xffffffffu, p1, off);
        }
        if (lane == 0) {
            float e0 = expf(p0), e1 = expf(p1);
            sal0[i] = e0; sal1[i] = e1;
            sslot[i] = slot;
            atomicAdd(&tsum0, e0); atomicAdd(&tsum1, e1);
        }
    }
    __syncthreads();

    float inv = (c < 64) ? (1.f / tsum0) : (1.f / tsum1);
    float agg = 0.f;
    for (int i = q; i < items; i += 4) {
        float al = ((c < 64) ? sal0[i] : sal1[i]) * inv;
        agg = fmaf(al, g_xl2[sslot[i] * HC + c], agg);
    }
    if (q > 0) sred2[q - 1][c] = agg;
    __syncthreads();
    if (q == 0) sO[c] = agg + sred2[0][c] + sred2[1][c] + sred2[2][c] + b2[c];
    __syncthreads();

    float r = 0.f;
    const float* Wf = Wfc + (q * 32) * HC + c;
    #pragma unroll
    for (int k = 0; k < 32; k++)
        r = fmaf(sO[q * 32 + k], Wf[k * HC], r);
    if (q > 0) sred2[q - 1][c] = r;
    __syncthreads();
    if (q == 0) out[c] = r + sred2[0][c] + sred2[1][c] + sred2[2][c] + bfc[c];
}

// ---------------- launch ----------------
extern "C" void kernel_launch(void* const* d_in, const int* in_sizes, int n_in,
                              void* d_out, int out_size) {
    const float* x    = (const float*)d_in[0];
    const int*   ei   = (const int*)  d_in[1];
    const float* ea   = (const float*)d_in[2];
    const int*   tgtp = (const int*)  d_in[3];
    const float* Wl1  = (const float*)d_in[4];
    const float* bl1  = (const float*)d_in[5];
    const float* Wr1  = (const float*)d_in[6];
    const float* br1  = (const float*)d_in[7];
    const float* We1  = (const float*)d_in[8];
    const float* att1 = (const float*)d_in[9];
    const float* b1   = (const float*)d_in[10];
    const float* Wl2  = (const float*)d_in[11];
    const float* bl2  = (const float*)d_in[12];
    const float* Wr2  = (const float*)d_in[13];
    const float* br2  = (const float*)d_in[14];
    const float* We2  = (const float*)d_in[15];
    const float* att2 = (const float*)d_in[16];
    const float* b2   = (const float*)d_in[17];
    const float* Wfc  = (const float*)d_in[18];
    const float* bfc  = (const float*)d_in[19];
    float* out = (float*)d_out;

    int E = in_sizes[1] / 2;
    const int* src = ei;
    const int* dst = ei + E;

    k_reset<<<64, 256>>>(tgtp, Wl2, Wr2, Wfc, x, Wl1, Wr1, We1, att1, bl1, br1, b1);
    k_scan1<<<592, 256>>>(src, dst, ea, tgtp, E);
    k_scan2<<<592, 256>>>(src, dst, ea, x, E);
    k_stats<<<STB, 256>>>(x, Wl1, bl1, Wr1, br1, We1, att1, E);
    k_gemm <<<64, 512>>>(Wl1, bl1, b1, Wl2, bl2, Wr2, br2);
    k_final<<<1, 512>>>(We2, att2, b2, Wfc, bfc, out);
    (void)n_in; (void)out_size;
}